// round 5
// baseline (speedup 1.0000x reference)
#include <cuda_runtime.h>

// Time-varying FIR, y = A0 + w*A1 two-accumulator split.
//   y[bb][t] = sum_k x[t-k] * (bL[n][k] + w*(bR[n][k]-bL[n][k])), n=t/80, w=(t%80)/80
// j-form (ascending x): y[u] = sum_j sx[u+j] * c49[j], c49[j] = coeff[49-j].
// R=8 samples/thread: one LDS.128 of (bL,d)x2 feeds 32 FFMA.

#define BATCH     8
#define N_FRAMES  3000
#define FPERIOD   80
#define T_LEN     (N_FRAMES * FPERIOD)   // 240000
#define TAPS      50
#define ORD       49

#define FPB       16                     // frames per block (divides 3000? 3000/16 no!)
// 3000 = 16*187.5 -> need FPB dividing 3000: use 15? 15*80=1200, TPF=10 -> 150 threads
#undef FPB
#define FPB       15                     // frames per block (3000/15 = 200 blocks)
#define SPB       (FPB * FPERIOD)        // 1200 samples per block
#define R         8                      // samples per thread
#define TPF       (FPERIOD / R)          // 10 threads per frame
#define THREADS   (FPB * TPF)            // 150 threads

#define SX_LEN    (ORD + SPB)            // 1249
#define SX_PAD    1256                   // pad for float4 over-read

__global__ __launch_bounds__(THREADS)
void azdf_kernel(const float* __restrict__ x,
                 const float* __restrict__ b,
                 float* __restrict__ y)
{
    __shared__ __align__(16) float sx[SX_PAD];
    __shared__ __align__(16) float sc[FPB * TAPS * 2];  // (c49[j], d49[j]) interleaved

    const int tid = threadIdx.x;
    const int bb  = blockIdx.y;
    const int f0  = blockIdx.x * FPB;
    const int t0  = f0 * FPERIOD;

    const float* xb  = x + (size_t)bb * T_LEN;
    const float* bbp = b + (size_t)bb * N_FRAMES * TAPS;

    // --- stage x window: sx[i] = x[t0 - 49 + i], zero left pad ---
    for (int i = tid; i < SX_LEN; i += THREADS) {
        int g = t0 - ORD + i;
        sx[i] = (g >= 0) ? xb[g] : 0.0f;
    }
    // --- stage reversed coeffs + diff: sc[f*100 + 2j] = bL[49-j], +1 = bR-bL ---
    for (int i = tid; i < FPB * TAPS; i += THREADS) {
        int f = i / TAPS;
        int j = i - f * TAPS;
        int k = ORD - j;
        float bl = bbp[(f0 + f) * TAPS + k];
        int f1 = f0 + f + 1;
        if (f1 > N_FRAMES - 1) f1 = N_FRAMES - 1;
        float br = bbp[f1 * TAPS + k];
        sc[f * (2 * TAPS) + 2 * j]     = bl;
        sc[f * (2 * TAPS) + 2 * j + 1] = br - bl;
    }
    __syncthreads();

    const int fi  = tid / TPF;            // frame within block
    const int sub = tid - fi * TPF;       // thread within frame
    const int p0  = sub * R;              // phase of first sample in frame
    const int s   = fi * FPERIOD + p0;    // first sample offset in block (mult of 8)

    // initial 8-sample window
    float4 wa = *(const float4*)&sx[s];
    float4 wb = *(const float4*)&sx[s + 4];
    float w0 = wa.x, w1 = wa.y, w2 = wa.z, w3 = wa.w;
    float w4 = wb.x, w5 = wb.y, w6 = wb.z, w7 = wb.w;

    float a00=0.f,a01=0.f,a02=0.f,a03=0.f,a04=0.f,a05=0.f,a06=0.f,a07=0.f; // sum x*bL
    float a10=0.f,a11=0.f,a12=0.f,a13=0.f,a14=0.f,a15=0.f,a16=0.f,a17=0.f; // sum x*diff

    const float4* cp = (const float4*)&sc[fi * (2 * TAPS)]; // 25 vec4, 2 taps each
    const float4* xq = (const float4*)&sx[s + R];           // prefetch stream

    float4 c, xp;
    #pragma unroll
    for (int j = 0; j < TAPS; j++) {
        if ((j & 1) == 0) c = cp[j >> 1];
        const float cb = (j & 1) ? c.z : c.x;
        const float cd = (j & 1) ? c.w : c.y;
        if ((j & 3) == 0) xp = xq[j >> 2];

        a00 = fmaf(w0, cb, a00);  a10 = fmaf(w0, cd, a10);
        a01 = fmaf(w1, cb, a01);  a11 = fmaf(w1, cd, a11);
        a02 = fmaf(w2, cb, a02);  a12 = fmaf(w2, cd, a12);
        a03 = fmaf(w3, cb, a03);  a13 = fmaf(w3, cd, a13);
        a04 = fmaf(w4, cb, a04);  a14 = fmaf(w4, cd, a14);
        a05 = fmaf(w5, cb, a05);  a15 = fmaf(w5, cd, a15);
        a06 = fmaf(w6, cb, a06);  a16 = fmaf(w6, cd, a16);
        a07 = fmaf(w7, cb, a07);  a17 = fmaf(w7, cd, a17);

        if (j < TAPS - 1) {
            const int ph = j & 3;   // compile-time after unroll
            float nx = (ph == 0) ? xp.x : (ph == 1) ? xp.y : (ph == 2) ? xp.z : xp.w;
            w0 = w1; w1 = w2; w2 = w3; w3 = w4;
            w4 = w5; w5 = w6; w6 = w7; w7 = nx;
        }
    }

    // epilogue: y = a0 + (phase/80)*a1 ; two STG.128
    const float inv = 1.0f / FPERIOD;
    float* yo = y + (size_t)bb * T_LEN + t0 + s;
    float4 r0, r1;
    r0.x = fmaf((float)(p0 + 0) * inv, a10, a00);
    r0.y = fmaf((float)(p0 + 1) * inv, a11, a01);
    r0.z = fmaf((float)(p0 + 2) * inv, a12, a02);
    r0.w = fmaf((float)(p0 + 3) * inv, a13, a03);
    r1.x = fmaf((float)(p0 + 4) * inv, a14, a04);
    r1.y = fmaf((float)(p0 + 5) * inv, a15, a05);
    r1.z = fmaf((float)(p0 + 6) * inv, a16, a06);
    r1.w = fmaf((float)(p0 + 7) * inv, a17, a07);
    *(float4*)yo       = r0;
    *(float4*)(yo + 4) = r1;
}

extern "C" void kernel_launch(void* const* d_in, const int* in_sizes, int n_in,
                              void* d_out, int out_size)
{
    const float* x = (const float*)d_in[0];
    const float* b = (const float*)d_in[1];
    if (in_sizes[0] != BATCH * T_LEN) {   // defensive input-order check
        const float* t = x; x = b; b = t;
    }
    dim3 grid(N_FRAMES / FPB, BATCH);    // 200 x 8
    azdf_kernel<<<grid, THREADS>>>(x, b, (float*)d_out);
}